// round 14
// baseline (speedup 1.0000x reference)
#include <cuda_runtime.h>
#include <math_constants.h>

// ---------------------------------------------------------------------------
// Exact 3-NN interpolation via grid ring-search — fused kernel v7.
// = R13 (ILP=2 pairs, 27.0us) with register pressure attacked so the ILP gain
// is no longer cancelled by occupancy loss:
//   - B-task params DERIVED from A (vsB=2vsA, gB=gA/2, baseB=baseA+gA^3,
//     C4B=2C4A, coff4B=coff4A+C4A) instead of a second switch
//   - B home cell derived as cB = cA>>1 (floor(floor(x)/2)=floor(x/2), x>=0)
//   - __launch_bounds__(256,5): hard 51-reg cap -> 5 blocks/SM guaranteed
//     resident (740-block grid barrier deadlock-safe), occ cap 62.5%
//
// Exactness unchanged (rel_err 6.083e-8 lineage): total (d2,row) lex order
// (rows unique per scale; duplicate voxels bitwise-equal d2, per-cell slots
// sorted by row); strict lex insert + REDUX head merge = stable
// jax.lax.top_k. Stop rule: after Chebyshev radius rr any unexamined center
// is >= (rr+0.5)*vs away; >=3 candidates strictly inside the conservatively
// shrunk bound => exact; full-grid fallback otherwise. Distance math:
// explicit __fmul_rn/__fadd_rn in reference op order.
// ---------------------------------------------------------------------------

#define NPTS   8192
#define INF_I  0x7fffffff
#define INF_FB 0x7f800000u

#define MB0 0
#define MB1 32768
#define MB2 (32768 + 4096)
#define MB3 (32768 + 4096 + 512)
#define MCELLS (32768 + 4096 + 512 + 64)

#define GRID     740                   // 5 blocks/SM * 148 SMs, all resident
#define TPB      256
#define NTHREADS (GRID * TPB)          // 189440
#define NWARPS   (NTHREADS / 32)       // 5920
#define NTASKS   (NPTS * 4)            // 32768 (point-major: task=point*4+scale)
#define NPAIRS   (NTASKS / 2)          // 16384
#define NROWS    20576                 // 16000 + 4000 + 512 + 64

__device__ int4     g_map[MCELLS];
__device__ unsigned g_cnt[2];
__device__ unsigned g_phase[2];        // monotone senses; never reset

__device__ __forceinline__ void grid_bar(int b)
{
    __syncthreads();
    if (threadIdx.x == 0) {
        volatile unsigned* ph = &g_phase[b];
        unsigned p0 = *ph;
        __threadfence();
        unsigned prev = atomicAdd(&g_cnt[b], 1u);
        if (prev == GRID - 1) {
            g_cnt[b] = 0;
            __threadfence();
            *ph = p0 + 1u;
        } else {
            while (*ph == p0) { }
        }
        __threadfence();
    }
    __syncthreads();
}

__device__ __forceinline__ bool diless(float da, int ia, float db, int ib) {
    return (da < db) || (da == db && ia < ib);
}

__device__ __forceinline__ void ins3(float d, int i,
                                     float& d0, int& i0,
                                     float& d1, int& i1,
                                     float& d2, int& i2) {
    if (diless(d, i, d2, i2)) {
        d2 = d; i2 = i;
        if (diless(d2, i2, d1, i1)) { float td = d1; d1 = d2; d2 = td; int ti = i1; i1 = i2; i2 = ti; }
        if (diless(d1, i1, d0, i0)) { float td = d0; d0 = d1; d1 = td; int ti = i0; i0 = i1; i1 = ti; }
    }
}

// Branch-free cell fetch: OOB -> INF quad; no data-dependent branch before
// the consumer, so back-to-back calls keep both LDGs in flight.
__device__ __forceinline__ int4 load_cell(int jx, int jy, int jz, int g, int base)
{
    if ((unsigned)jx < (unsigned)g && (unsigned)jy < (unsigned)g &&
        (unsigned)jz < (unsigned)g)
        return g_map[base + (jx * g + jy) * g + jz];
    return make_int4(INF_I, INF_I, INF_I, INF_I);
}

__device__ __forceinline__ void accum_cell(
    int4 s, int jx, int jy, int jz,
    float vs, float OFF, float HALF,
    float px, float py, float pz,
    float& d0, int& r0, float& d1, int& r1, float& d2, int& r2)
{
    if (s.x == INF_I) return;
    float qx = __fadd_rn(__fadd_rn(__fmul_rn((float)jx, vs), OFF), HALF);
    float qy = __fadd_rn(__fadd_rn(__fmul_rn((float)jy, vs), OFF), HALF);
    float qz = __fadd_rn(__fadd_rn(__fmul_rn((float)jz, vs), OFF), HALF);
    float ddx = px - qx, ddy = py - qy, ddz = pz - qz;
    float dd = __fadd_rn(__fadd_rn(__fmul_rn(ddx, ddx), __fmul_rn(ddy, ddy)),
                         __fmul_rn(ddz, ddz));
    ins3(dd, s.x, d0, r0, d1, r1, d2, r2);
    if (s.y != INF_I) {
        ins3(dd, s.y, d0, r0, d1, r1, d2, r2);
        if (s.z != INF_I) ins3(dd, s.z, d0, r0, d1, r1, d2, r2);
    }
}

// Warp-cooperative ring expansion for tasks failing the rr=1 bound (rare).
__device__ __forceinline__ void ring_fallback(
    int lane, int g, int base, float vs, float OFF, float HALF,
    float px, float py, float pz, int cx, int cy, int cz,
    float& d0, int& r0, float& d1, int& r1, float& d2, int& r2)
{
    int rr = 2;
    while (true) {
        int side = 2 * rr + 1;
        int nc = side * side * side;
        for (int i = lane; i < nc; i += 32) {
            int t = i;
            int dz = t % side; t /= side;
            int dy = t % side;
            int dx = t / side;
            dx -= rr; dy -= rr; dz -= rr;
            int ch = max(max(abs(dx), abs(dy)), abs(dz));
            if (ch < rr) continue;                   // interior already done
            int4 s = load_cell(cx + dx, cy + dy, cz + dz, g, base);
            accum_cell(s, cx + dx, cy + dy, cz + dz, vs, OFF, HALF,
                       px, py, pz, d0, r0, d1, r1, d2, r2);
        }
        float bb  = ((float)rr + 0.5f) * vs * 0.999999f;
        float bb2 = bb * bb;
        int c = (int)(d0 < bb2) + (int)(d1 < bb2) + (int)(d2 < bb2);
        if (__reduce_add_sync(0xffffffffu, c) >= 3) break;
        if (rr >= g) break;                          // full grid -> exact
        rr++;
    }
}

// ---------------------------------------------------------------------------
__global__ void __launch_bounds__(TPB, 5)
fused(const float* __restrict__ pts,
      const int* __restrict__ x0, const int* __restrict__ x1,
      const int* __restrict__ x2, const int* __restrict__ x3,
      const float* __restrict__ f0, const float* __restrict__ f1,
      const float* __restrict__ f2, const float* __restrict__ f3,
      float* __restrict__ out)
{
    int gtid = blockIdx.x * TPB + threadIdx.x;
    const float OFF = -0.48f;                        // (-0.5*0.015f)*64, exact

    // ---- phase 0: init occupancy maps ----
    for (int i = gtid; i < MCELLS; i += NTHREADS)
        g_map[i] = make_int4(INF_I, INF_I, INF_I, INF_I);
    grid_bar(0);

    // ---- phase 1: scatter rows (3 lowest rows per cell, sorted) ----
    if (gtid < NROWS) {
        int t = gtid;
        const int* inds; int g, base, row;
        if (t < 16000)      { inds = x0; g = 32; base = MB0; row = t; }
        else if (t < 20000) { inds = x1; g = 16; base = MB1; row = t - 16000; }
        else if (t < 20512) { inds = x2; g = 8;  base = MB2; row = t - 20000; }
        else                { inds = x3; g = 4;  base = MB3; row = t - 20512; }
        int4 v = ((const int4*)inds)[row];           // [batch, ix, iy, iz]
        int* s = (int*)&g_map[base + (v.y * g + v.z) * g + v.w];
        int cur = row;
#pragma unroll
        for (int k = 0; k < 3; k++) {
            int old = atomicMin(&s[k], cur);
            cur = max(old, cur);
            if (cur == INF_I) break;
        }
    }
    grid_bar(1);

    // ---- phase 2: ILP=2 task pairs (same point; scales s, s+1) ----
    int warp = gtid >> 5;
    int lane = threadIdx.x & 31;

#pragma unroll 1
    for (int p = warp; p < NPAIRS; p += NWARPS) {
        int taskA = 2 * p;                           // point-major ids
        int point = taskA >> 2;
        int sA = taskA & 3;                          // 0 or 2

        // A params via tiny switch; B params DERIVED (saves live registers)
        const float *fA, *fB; float vsA; int gA, baseA, C4A, coff4A;
        if (sA == 0) { fA = f0; fB = f1; vsA = 0.03f; gA = 32; baseA = MB0; C4A = 8;  coff4A = 0;  }
        else         { fA = f2; fB = f3; vsA = 0.12f; gA = 8;  baseA = MB2; C4A = 32; coff4A = 24; }
        float vsB   = vsA * 2.0f;                    // exact (powers of 2)
        int   gB    = gA >> 1;
        int   baseB = baseA + gA * gA * gA;
        int   C4B   = C4A * 2;
        int   coff4B = coff4A + C4A;
        const float HA = 0.5f * vsA, HB = vsA;       // HB = 0.5*vsB = vsA

        float px = __ldg(&pts[point * 3 + 0]);
        float py = __ldg(&pts[point * 3 + 1]);
        float pz = __ldg(&pts[point * 3 + 2]);

        int cxA = min(gA - 1, max(0, (int)floorf((px - OFF) / vsA)));
        int cyA = min(gA - 1, max(0, (int)floorf((py - OFF) / vsA)));
        int czA = min(gA - 1, max(0, (int)floorf((pz - OFF) / vsA)));
        // B home cell: (p-OFF)/vsB = ((p-OFF)/vsA)/2 and x>=0 =>
        // floor(x/2) = floor(floor(x)/2); clamp composes (31>>1=15 etc).
        int cxB = cxA >> 1, cyB = cyA >> 1, czB = czA >> 1;

        float dA0 = CUDART_INF_F, dA1 = CUDART_INF_F, dA2 = CUDART_INF_F;
        int   rA0 = INF_I,        rA1 = INF_I,        rA2 = INF_I;
        float dB0 = CUDART_INF_F, dB1 = CUDART_INF_F, dB2 = CUDART_INF_F;
        int   rB0 = INF_I,        rB1 = INF_I,        rB2 = INF_I;

        // rr=1: lane < 27 owns one cube offset, used for BOTH tasks;
        // both LDGs issue before either result is consumed.
        if (lane < 27) {
            int dz = lane % 3 - 1;
            int r3 = lane / 3;
            int dy = r3 % 3 - 1;
            int dx = r3 / 3 - 1;
            int jxA = cxA + dx, jyA = cyA + dy, jzA = czA + dz;
            int jxB = cxB + dx, jyB = cyB + dy, jzB = czB + dz;
            int4 sAq = load_cell(jxA, jyA, jzA, gA, baseA);
            int4 sBq = load_cell(jxB, jyB, jzB, gB, baseB);
            accum_cell(sAq, jxA, jyA, jzA, vsA, OFF, HA, px, py, pz,
                       dA0, rA0, dA1, rA1, dA2, rA2);
            accum_cell(sBq, jxB, jyB, jzB, vsB, OFF, HB, px, py, pz,
                       dB0, rB0, dB1, rB1, dB2, rB2);
        }

        // fused stop test: one packed REDUX for both tasks
        {
            float bA = 1.5f * vsA * 0.999999f; float bA2 = bA * bA;
            float bB = 1.5f * vsB * 0.999999f; float bB2 = bB * bB;
            int cA = (int)(dA0 < bA2) + (int)(dA1 < bA2) + (int)(dA2 < bA2);
            int cB = (int)(dB0 < bB2) + (int)(dB1 < bB2) + (int)(dB2 < bB2);
            int tot = __reduce_add_sync(0xffffffffu, cA + (cB << 8));
            if ((tot & 0xff) < 3)
                ring_fallback(lane, gA, baseA, vsA, OFF, HA, px, py, pz,
                              cxA, cyA, czA, dA0, rA0, dA1, rA1, dA2, rA2);
            if ((tot >> 8) < 3)
                ring_fallback(lane, gB, baseB, vsB, OFF, HB, px, py, pz,
                              cxB, cyB, czB, dB0, rB0, dB1, rB1, dB2, rB2);
        }

        // REDUX 3-way head merges, A/B issue interleaved.
        unsigned hA0 = __float_as_uint(dA0), hA1 = __float_as_uint(dA1),
                 hA2 = __float_as_uint(dA2);
        unsigned hB0 = __float_as_uint(dB0), hB1 = __float_as_uint(dB1),
                 hB2 = __float_as_uint(dB2);
        float wdA[3], wdB[3]; int wrA[3], wrB[3];
#pragma unroll
        for (int k = 0; k < 3; k++) {
            unsigned mA  = __reduce_min_sync(0xffffffffu, hA0);
            unsigned mB  = __reduce_min_sync(0xffffffffu, hB0);
            unsigned rmA = __reduce_min_sync(0xffffffffu,
                               (hA0 == mA) ? (unsigned)rA0 : (unsigned)INF_I);
            unsigned rmB = __reduce_min_sync(0xffffffffu,
                               (hB0 == mB) ? (unsigned)rB0 : (unsigned)INF_I);
            wdA[k] = __uint_as_float(mA); wrA[k] = (int)rmA;
            wdB[k] = __uint_as_float(mB); wrB[k] = (int)rmB;
            if (hA0 == mA && (unsigned)rA0 == rmA) {   // pop my head (A)
                hA0 = hA1; rA0 = rA1; hA1 = hA2; rA1 = rA2;
                hA2 = INF_FB; rA2 = INF_I;
            }
            if (hB0 == mB && (unsigned)rB0 == rmB) {   // pop my head (B)
                hB0 = hB1; rB0 = rB1; hB1 = hB2; rB1 = rB2;
                hB2 = INF_FB; rB2 = INF_I;
            }
        }

        // weights, A/B interleaved (independent MUFU chains)
        float aA0 = 1.0f / (wdA[0] + 1e-8f);
        float aB0 = 1.0f / (wdB[0] + 1e-8f);
        float aA1 = 1.0f / (wdA[1] + 1e-8f);
        float aB1 = 1.0f / (wdB[1] + 1e-8f);
        float aA2 = 1.0f / (wdA[2] + 1e-8f);
        float aB2 = 1.0f / (wdB[2] + 1e-8f);
        float invA = 1.0f / (aA0 + aA1 + aA2);
        float invB = 1.0f / (aB0 + aB1 + aB2);
        float wA0 = aA0 * invA, wA1 = aA1 * invA, wA2 = aA2 * invA;
        float wB0 = aB0 * invB, wB1 = aB1 * invB, wB2 = aB2 * invB;

        // gathers back-to-back (independent load streams)
        {
            const float4* q0 = (const float4*)fA + (size_t)wrA[0] * C4A;
            const float4* q1 = (const float4*)fA + (size_t)wrA[1] * C4A;
            const float4* q2 = (const float4*)fA + (size_t)wrA[2] * C4A;
            float4* o = (float4*)out + (size_t)point * 120 + coff4A;
            for (int c = lane; c < C4A; c += 32) {
                float4 a = q0[c], b = q1[c], d = q2[c], r;
                r.x = wA0 * a.x + wA1 * b.x + wA2 * d.x;
                r.y = wA0 * a.y + wA1 * b.y + wA2 * d.y;
                r.z = wA0 * a.z + wA1 * b.z + wA2 * d.z;
                r.w = wA0 * a.w + wA1 * b.w + wA2 * d.w;
                o[c] = r;
            }
        }
        {
            const float4* q0 = (const float4*)fB + (size_t)wrB[0] * C4B;
            const float4* q1 = (const float4*)fB + (size_t)wrB[1] * C4B;
            const float4* q2 = (const float4*)fB + (size_t)wrB[2] * C4B;
            float4* o = (float4*)out + (size_t)point * 120 + coff4B;
            for (int c = lane; c < C4B; c += 32) {
                float4 a = q0[c], b = q1[c], d = q2[c], r;
                r.x = wB0 * a.x + wB1 * b.x + wB2 * d.x;
                r.y = wB0 * a.y + wB1 * b.y + wB2 * d.y;
                r.z = wB0 * a.z + wB1 * b.z + wB2 * d.z;
                r.w = wB0 * a.w + wB1 * b.w + wB2 * d.w;
                o[c] = r;
            }
        }
    }
}

// ---------------------------------------------------------------------------
// Inputs identified by element count (all ten distinct):
//   points 24576 | batch_ids 8192 (all-zero, unused by reference)
//   indices: 64000 / 16000 / 2048 / 256
//   feats:   512000 / 256000 / 65536 / 16384
// ---------------------------------------------------------------------------
extern "C" void kernel_launch(void* const* d_in, const int* in_sizes, int n_in,
                              void* d_out, int out_size)
{
    const float* points = nullptr;
    const int* idx[4] = {nullptr, nullptr, nullptr, nullptr};
    const float* feats[4] = {nullptr, nullptr, nullptr, nullptr};

    for (int i = 0; i < n_in; i++) {
        switch (in_sizes[i]) {
            case 24576:  points   = (const float*)d_in[i]; break;
            case 64000:  idx[0]   = (const int*)d_in[i];   break;
            case 16000:  idx[1]   = (const int*)d_in[i];   break;
            case 2048:   idx[2]   = (const int*)d_in[i];   break;
            case 256:    idx[3]   = (const int*)d_in[i];   break;
            case 512000: feats[0] = (const float*)d_in[i]; break;
            case 256000: feats[1] = (const float*)d_in[i]; break;
            case 65536:  feats[2] = (const float*)d_in[i]; break;
            case 16384:  feats[3] = (const float*)d_in[i]; break;
            default: break; // batch_ids unused
        }
    }

    fused<<<GRID, TPB>>>(points, idx[0], idx[1], idx[2], idx[3],
                         feats[0], feats[1], feats[2], feats[3],
                         (float*)d_out);
}

// round 15
// speedup vs baseline: 1.0022x; 1.0022x over previous
#include <cuda_runtime.h>
#include <math_constants.h>

// ---------------------------------------------------------------------------
// Exact 3-NN interpolation via grid ring-search — fused kernel v8.
// Base = R13 (best, 27.0us): persistent grid, two barriers, ILP=2 task pairs
// (same point, scales s/s+1), branch-free paired map loads, packed stop
// REDUX, interleaved REDUX head merges. Changes vs R13 (targeting the
// straggler tail that static striding exposes at ~3 pairs/warp):
//   1. DYNAMIC warp-level scheduling: one atomicAdd ticket per pair -> warps
//      that draw expensive fallback pairs don't also queue 2 more behind
//      them while other warps idle (schedule-independent output).
//   2. Fused A/B gather loop: out offsets are contiguous (coff4B =
//      coff4A+C4A), so one slot loop covers both tasks; kills the half-empty
//      warp iterations for C4A=8/C4B=16 pairs.
//
// Exactness unchanged (rel_err 6.083e-8 lineage): candidates form a total
// (d2,row) lexicographic order (rows unique per scale; duplicate voxels give
// bitwise-equal d2, per-cell slots sorted by row); strict lex insert + REDUX
// head merge = stable jax.lax.top_k. Stop rule: after Chebyshev radius rr,
// any unexamined center is >= (rr+0.5)*vs away; >=3 candidates strictly
// inside the conservatively-shrunk bound => exact; full-grid fallback
// otherwise. Distance math: explicit __fmul_rn/__fadd_rn, reference order.
// ---------------------------------------------------------------------------

#define NPTS   8192
#define INF_I  0x7fffffff
#define INF_FB 0x7f800000u

#define MB0 0
#define MB1 32768
#define MB2 (32768 + 4096)
#define MB3 (32768 + 4096 + 512)
#define MCELLS (32768 + 4096 + 512 + 64)

#define GRID     592                   // 4 blocks/SM * 148 SMs, all resident
#define TPB      256
#define NTHREADS (GRID * TPB)          // 151552
#define NTASKS   (NPTS * 4)            // 32768 (point-major: task=point*4+scale)
#define NPAIRS   (NTASKS / 2)          // 16384
#define NROWS    20576                 // 16000 + 4000 + 512 + 64

__device__ int4     g_map[MCELLS];
__device__ unsigned g_task;            // dynamic pair ticket counter
__device__ unsigned g_cnt[2];
__device__ unsigned g_phase[2];        // monotone senses; never reset

__device__ __forceinline__ void grid_bar(int b)
{
    __syncthreads();
    if (threadIdx.x == 0) {
        volatile unsigned* ph = &g_phase[b];
        unsigned p0 = *ph;
        __threadfence();
        unsigned prev = atomicAdd(&g_cnt[b], 1u);
        if (prev == GRID - 1) {
            g_cnt[b] = 0;
            __threadfence();
            *ph = p0 + 1u;
        } else {
            while (*ph == p0) { }
        }
        __threadfence();
    }
    __syncthreads();
}

__device__ __forceinline__ bool diless(float da, int ia, float db, int ib) {
    return (da < db) || (da == db && ia < ib);
}

__device__ __forceinline__ void ins3(float d, int i,
                                     float& d0, int& i0,
                                     float& d1, int& i1,
                                     float& d2, int& i2) {
    if (diless(d, i, d2, i2)) {
        d2 = d; i2 = i;
        if (diless(d2, i2, d1, i1)) { float td = d1; d1 = d2; d2 = td; int ti = i1; i1 = i2; i2 = ti; }
        if (diless(d1, i1, d0, i0)) { float td = d0; d0 = d1; d1 = td; int ti = i0; i0 = i1; i1 = ti; }
    }
}

// Branch-free cell fetch: OOB -> INF quad; no data-dependent branch before
// the consumer, so back-to-back calls keep both LDGs in flight.
__device__ __forceinline__ int4 load_cell(int jx, int jy, int jz, int g, int base)
{
    if ((unsigned)jx < (unsigned)g && (unsigned)jy < (unsigned)g &&
        (unsigned)jz < (unsigned)g)
        return g_map[base + (jx * g + jy) * g + jz];
    return make_int4(INF_I, INF_I, INF_I, INF_I);
}

__device__ __forceinline__ void accum_cell(
    int4 s, int jx, int jy, int jz,
    float vs, float OFF, float HALF,
    float px, float py, float pz,
    float& d0, int& r0, float& d1, int& r1, float& d2, int& r2)
{
    if (s.x == INF_I) return;
    float qx = __fadd_rn(__fadd_rn(__fmul_rn((float)jx, vs), OFF), HALF);
    float qy = __fadd_rn(__fadd_rn(__fmul_rn((float)jy, vs), OFF), HALF);
    float qz = __fadd_rn(__fadd_rn(__fmul_rn((float)jz, vs), OFF), HALF);
    float ddx = px - qx, ddy = py - qy, ddz = pz - qz;
    float dd = __fadd_rn(__fadd_rn(__fmul_rn(ddx, ddx), __fmul_rn(ddy, ddy)),
                         __fmul_rn(ddz, ddz));
    ins3(dd, s.x, d0, r0, d1, r1, d2, r2);
    if (s.y != INF_I) {
        ins3(dd, s.y, d0, r0, d1, r1, d2, r2);
        if (s.z != INF_I) ins3(dd, s.z, d0, r0, d1, r1, d2, r2);
    }
}

// Warp-cooperative ring expansion for tasks failing the rr=1 bound (rare).
__device__ __forceinline__ void ring_fallback(
    int lane, int g, int base, float vs, float OFF, float HALF,
    float px, float py, float pz, int cx, int cy, int cz,
    float& d0, int& r0, float& d1, int& r1, float& d2, int& r2)
{
    int rr = 2;
    while (true) {
        int side = 2 * rr + 1;
        int nc = side * side * side;
        for (int i = lane; i < nc; i += 32) {
            int t = i;
            int dz = t % side; t /= side;
            int dy = t % side;
            int dx = t / side;
            dx -= rr; dy -= rr; dz -= rr;
            int ch = max(max(abs(dx), abs(dy)), abs(dz));
            if (ch < rr) continue;                   // interior already done
            int4 s = load_cell(cx + dx, cy + dy, cz + dz, g, base);
            accum_cell(s, cx + dx, cy + dy, cz + dz, vs, OFF, HALF,
                       px, py, pz, d0, r0, d1, r1, d2, r2);
        }
        float bb  = ((float)rr + 0.5f) * vs * 0.999999f;
        float bb2 = bb * bb;
        int c = (int)(d0 < bb2) + (int)(d1 < bb2) + (int)(d2 < bb2);
        if (__reduce_add_sync(0xffffffffu, c) >= 3) break;
        if (rr >= g) break;                          // full grid -> exact
        rr++;
    }
}

// ---------------------------------------------------------------------------
__global__ void __launch_bounds__(TPB, 4)
fused(const float* __restrict__ pts,
      const int* __restrict__ x0, const int* __restrict__ x1,
      const int* __restrict__ x2, const int* __restrict__ x3,
      const float* __restrict__ f0, const float* __restrict__ f1,
      const float* __restrict__ f2, const float* __restrict__ f3,
      float* __restrict__ out)
{
    int gtid = blockIdx.x * TPB + threadIdx.x;
    const float OFF = -0.48f;                        // (-0.5*0.015f)*64, exact

    // ---- phase 0: init occupancy maps + ticket counter ----
    if (gtid == 0) g_task = 0;
    for (int i = gtid; i < MCELLS; i += NTHREADS)
        g_map[i] = make_int4(INF_I, INF_I, INF_I, INF_I);
    grid_bar(0);

    // ---- phase 1: scatter rows (3 lowest rows per cell, sorted) ----
    if (gtid < NROWS) {
        int t = gtid;
        const int* inds; int g, base, row;
        if (t < 16000)      { inds = x0; g = 32; base = MB0; row = t; }
        else if (t < 20000) { inds = x1; g = 16; base = MB1; row = t - 16000; }
        else if (t < 20512) { inds = x2; g = 8;  base = MB2; row = t - 20000; }
        else                { inds = x3; g = 4;  base = MB3; row = t - 20512; }
        int4 v = ((const int4*)inds)[row];           // [batch, ix, iy, iz]
        int* s = (int*)&g_map[base + (v.y * g + v.z) * g + v.w];
        int cur = row;
#pragma unroll
        for (int k = 0; k < 3; k++) {
            int old = atomicMin(&s[k], cur);
            cur = max(old, cur);
            if (cur == INF_I) break;
        }
    }
    grid_bar(1);

    // ---- phase 2: dynamically scheduled ILP=2 task pairs ----
    int lane = threadIdx.x & 31;

    while (true) {
        unsigned p;
        if (lane == 0) p = atomicAdd(&g_task, 1u);
        p = __shfl_sync(0xffffffffu, p, 0);
        if (p >= NPAIRS) break;

        int taskA = 2 * (int)p;                      // point-major ids
        int point = taskA >> 2;
        int sA = taskA & 3;                          // 0 or 2

        // A params via tiny switch; B params derived (register-lean)
        const float *fA, *fB; float vsA; int gA, baseA, C4A, coff4A;
        if (sA == 0) { fA = f0; fB = f1; vsA = 0.03f; gA = 32; baseA = MB0; C4A = 8;  coff4A = 0;  }
        else         { fA = f2; fB = f3; vsA = 0.12f; gA = 8;  baseA = MB2; C4A = 32; coff4A = 24; }
        float vsB   = vsA * 2.0f;                    // exact (powers of 2)
        int   gB    = gA >> 1;
        int   baseB = baseA + gA * gA * gA;
        int   C4B   = C4A * 2;
        const float HA = 0.5f * vsA, HB = vsA;       // HB = 0.5*vsB

        float px = __ldg(&pts[point * 3 + 0]);
        float py = __ldg(&pts[point * 3 + 1]);
        float pz = __ldg(&pts[point * 3 + 2]);

        int cxA = min(gA - 1, max(0, (int)floorf((px - OFF) / vsA)));
        int cyA = min(gA - 1, max(0, (int)floorf((py - OFF) / vsA)));
        int czA = min(gA - 1, max(0, (int)floorf((pz - OFF) / vsA)));
        // floor(x/2) = floor(floor(x)/2) for x>=0; clamp composes.
        int cxB = cxA >> 1, cyB = cyA >> 1, czB = czA >> 1;

        float dA0 = CUDART_INF_F, dA1 = CUDART_INF_F, dA2 = CUDART_INF_F;
        int   rA0 = INF_I,        rA1 = INF_I,        rA2 = INF_I;
        float dB0 = CUDART_INF_F, dB1 = CUDART_INF_F, dB2 = CUDART_INF_F;
        int   rB0 = INF_I,        rB1 = INF_I,        rB2 = INF_I;

        // rr=1: lane < 27 owns one cube offset for BOTH tasks; both LDGs
        // issue before either result is consumed.
        if (lane < 27) {
            int dz = lane % 3 - 1;
            int r3 = lane / 3;
            int dy = r3 % 3 - 1;
            int dx = r3 / 3 - 1;
            int jxA = cxA + dx, jyA = cyA + dy, jzA = czA + dz;
            int jxB = cxB + dx, jyB = cyB + dy, jzB = czB + dz;
            int4 sAq = load_cell(jxA, jyA, jzA, gA, baseA);
            int4 sBq = load_cell(jxB, jyB, jzB, gB, baseB);
            accum_cell(sAq, jxA, jyA, jzA, vsA, OFF, HA, px, py, pz,
                       dA0, rA0, dA1, rA1, dA2, rA2);
            accum_cell(sBq, jxB, jyB, jzB, vsB, OFF, HB, px, py, pz,
                       dB0, rB0, dB1, rB1, dB2, rB2);
        }

        // fused stop test: one packed REDUX for both tasks
        {
            float bA = 1.5f * vsA * 0.999999f; float bA2 = bA * bA;
            float bB = 1.5f * vsB * 0.999999f; float bB2 = bB * bB;
            int cA = (int)(dA0 < bA2) + (int)(dA1 < bA2) + (int)(dA2 < bA2);
            int cB = (int)(dB0 < bB2) + (int)(dB1 < bB2) + (int)(dB2 < bB2);
            int tot = __reduce_add_sync(0xffffffffu, cA + (cB << 8));
            if ((tot & 0xff) < 3)
                ring_fallback(lane, gA, baseA, vsA, OFF, HA, px, py, pz,
                              cxA, cyA, czA, dA0, rA0, dA1, rA1, dA2, rA2);
            if ((tot >> 8) < 3)
                ring_fallback(lane, gB, baseB, vsB, OFF, HB, px, py, pz,
                              cxB, cyB, czB, dB0, rB0, dB1, rB1, dB2, rB2);
        }

        // REDUX 3-way head merges, A/B issue interleaved.
        unsigned hA0 = __float_as_uint(dA0), hA1 = __float_as_uint(dA1),
                 hA2 = __float_as_uint(dA2);
        unsigned hB0 = __float_as_uint(dB0), hB1 = __float_as_uint(dB1),
                 hB2 = __float_as_uint(dB2);
        float wdA[3], wdB[3]; int wrA[3], wrB[3];
#pragma unroll
        for (int k = 0; k < 3; k++) {
            unsigned mA  = __reduce_min_sync(0xffffffffu, hA0);
            unsigned mB  = __reduce_min_sync(0xffffffffu, hB0);
            unsigned rmA = __reduce_min_sync(0xffffffffu,
                               (hA0 == mA) ? (unsigned)rA0 : (unsigned)INF_I);
            unsigned rmB = __reduce_min_sync(0xffffffffu,
                               (hB0 == mB) ? (unsigned)rB0 : (unsigned)INF_I);
            wdA[k] = __uint_as_float(mA); wrA[k] = (int)rmA;
            wdB[k] = __uint_as_float(mB); wrB[k] = (int)rmB;
            if (hA0 == mA && (unsigned)rA0 == rmA) {   // pop my head (A)
                hA0 = hA1; rA0 = rA1; hA1 = hA2; rA1 = rA2;
                hA2 = INF_FB; rA2 = INF_I;
            }
            if (hB0 == mB && (unsigned)rB0 == rmB) {   // pop my head (B)
                hB0 = hB1; rB0 = rB1; hB1 = hB2; rB1 = rB2;
                hB2 = INF_FB; rB2 = INF_I;
            }
        }

        // weights, A/B interleaved (independent MUFU chains)
        float aA0 = 1.0f / (wdA[0] + 1e-8f);
        float aB0 = 1.0f / (wdB[0] + 1e-8f);
        float aA1 = 1.0f / (wdA[1] + 1e-8f);
        float aB1 = 1.0f / (wdB[1] + 1e-8f);
        float aA2 = 1.0f / (wdA[2] + 1e-8f);
        float aB2 = 1.0f / (wdB[2] + 1e-8f);
        float invA = 1.0f / (aA0 + aA1 + aA2);
        float invB = 1.0f / (aB0 + aB1 + aB2);
        float wA0 = aA0 * invA, wA1 = aA1 * invA, wA2 = aA2 * invA;
        float wB0 = aB0 * invB, wB1 = aB1 * invB, wB2 = aB2 * invB;

        // fused A/B gather: out offsets are contiguous (coff4B = coff4A+C4A),
        // so slot s in [0, 3*C4A) writes out[point*120 + coff4A + s], reading
        // from A when s < C4A else from B (c = s - C4A).
        {
            int nslots = C4A * 3;                    // C4A + C4B
            float4* o = (float4*)out + (size_t)point * 120 + coff4A;
            for (int s = lane; s < nslots; s += 32) {
                bool isA = s < C4A;
                int  c   = isA ? s : (s - C4A);
                const float4* F = (const float4*)(isA ? fA : fB);
                int C4v  = isA ? C4A : C4B;
                int i0   = isA ? wrA[0] : wrB[0];
                int i1   = isA ? wrA[1] : wrB[1];
                int i2   = isA ? wrA[2] : wrB[2];
                float u0 = isA ? wA0 : wB0;
                float u1 = isA ? wA1 : wB1;
                float u2 = isA ? wA2 : wB2;
                float4 a = F[(size_t)i0 * C4v + c];
                float4 b = F[(size_t)i1 * C4v + c];
                float4 d = F[(size_t)i2 * C4v + c];
                float4 r;
                r.x = u0 * a.x + u1 * b.x + u2 * d.x;
                r.y = u0 * a.y + u1 * b.y + u2 * d.y;
                r.z = u0 * a.z + u1 * b.z + u2 * d.z;
                r.w = u0 * a.w + u1 * b.w + u2 * d.w;
                o[s] = r;
            }
        }
    }
}

// ---------------------------------------------------------------------------
// Inputs identified by element count (all ten distinct):
//   points 24576 | batch_ids 8192 (all-zero, unused by reference)
//   indices: 64000 / 16000 / 2048 / 256
//   feats:   512000 / 256000 / 65536 / 16384
// ---------------------------------------------------------------------------
extern "C" void kernel_launch(void* const* d_in, const int* in_sizes, int n_in,
                              void* d_out, int out_size)
{
    const float* points = nullptr;
    const int* idx[4] = {nullptr, nullptr, nullptr, nullptr};
    const float* feats[4] = {nullptr, nullptr, nullptr, nullptr};

    for (int i = 0; i < n_in; i++) {
        switch (in_sizes[i]) {
            case 24576:  points   = (const float*)d_in[i]; break;
            case 64000:  idx[0]   = (const int*)d_in[i];   break;
            case 16000:  idx[1]   = (const int*)d_in[i];   break;
            case 2048:   idx[2]   = (const int*)d_in[i];   break;
            case 256:    idx[3]   = (const int*)d_in[i];   break;
            case 512000: feats[0] = (const float*)d_in[i]; break;
            case 256000: feats[1] = (const float*)d_in[i]; break;
            case 65536:  feats[2] = (const float*)d_in[i]; break;
            case 16384:  feats[3] = (const float*)d_in[i]; break;
            default: break; // batch_ids unused
        }
    }

    fused<<<GRID, TPB>>>(points, idx[0], idx[1], idx[2], idx[3],
                         feats[0], feats[1], feats[2], feats[3],
                         (float*)d_out);
}